// round 12
// baseline (speedup 1.0000x reference)
#include <cuda_runtime.h>
#include <math.h>

#define POOL 7
#define ROI_SCALE 0.0625f
#define WPB 8        // warps per block
#define CH  8        // channels per warp
#define NGR 32       // channel groups = C/CH
#define CMW 68       // smem row pitch in floats (16B-aligned, 66 used)

// grid = (NGR/WPB, N) = (4, N); one warp = one (roi, 8-channel group), all 7
// row-bins. Lanes: h=lane>>4 selects plane parity, li=lane&15 covers 64 cols
// as float4 -> 4 LDG.128 per row for 8 planes (step s loads plane 2s+h).
// Per bin: accumulate column maxima, flush 4xSTS.128 to 2KB/warp smem, lanes
// reduce 2 of the 56 (ch,pw) outputs (x-geometry precomputed once per task).
__global__ __launch_bounds__(32 * WPB, 4)
void roipool_kernel(const float* __restrict__ feat,
                    const float* __restrict__ rois,
                    float* __restrict__ out,
                    int N, int C, int write_bid) {
    __shared__ float cm[WPB][CH * CMW];
    __shared__ int g[10];   // b,px,py,qx, lenx,leny, psx,psy, pad0x,pad0y
    const int H = 64, W = 64;

    int n = blockIdx.y;

    // Fused second output of the reference tuple: batch ids as floats.
    if (write_bid && blockIdx.x == 0 && blockIdx.y == 0 && threadIdx.x < N) {
        out[N * C * POOL * POOL + threadIdx.x] =
            (float)((int)rois[threadIdx.x * 5]);
    }

    if (threadIdx.x == 0) {
        const float* r = rois + n * 5;
        // jnp.round = round-half-to-even = __float2int_rn
        int px = __float2int_rn(r[1] * ROI_SCALE);
        int py = __float2int_rn(r[2] * ROI_SCALE);
        int qx = __float2int_rn(r[3] * ROI_SCALE);
        int qy = __float2int_rn(r[4] * ROI_SCALE);
        int lenx = max(qx - px + 1, 1);
        int leny = max(qy - py + 1, 1);
        int psx  = (lenx + POOL - 1) / POOL;
        int psy  = (leny + POOL - 1) / POOL;
        g[0] = (int)r[0];
        g[1] = px; g[2] = py; g[3] = qx;
        g[4] = lenx; g[5] = leny;
        g[6] = psx; g[7] = psy;
        g[8] = (psx * POOL - lenx) / 2;
        g[9] = (psy * POOL - leny) / 2;
    }
    __syncthreads();

    int warp = threadIdx.x >> 5;
    int lane = threadIdx.x & 31;
    int cg   = blockIdx.x * WPB + warp;   // channel group 0..31

    int px = g[1], py = g[2], qx = g[3];
    int lenx = g[4], leny = g[5], psx = g[6], psy = g[7];
    int pad0x = g[8], pad0y = g[9];

    int h  = lane >> 4;                   // plane parity
    int li = lane & 15;                   // float4 column index
    int px4 = px & ~3;                    // 16B-aligned load base
    int dpx = px - px4;                   // 0..3
    bool act = (px4 + 4 * li) <= qx;

    // lane's load pointer: plane (cg*8 + h), row py, col px4 + 4*li
    const float* bp = feat + (unsigned)((g[0] * C + cg * CH + h) * (H * W))
                    + (unsigned)(py * W + px4 + 4 * li);

    float* cw = cm[warp];

    // ---- reduce roles: ph-invariant x-geometry, computed once ----
    int ch0 = lane / POOL, pw0 = lane - ch0 * POOL;   // bins 0..31
    int bi1 = lane + 32;                               // bins 32..55
    int ch1 = bi1 / POOL, pw1 = bi1 - ch1 * POOL;
    bool r1 = bi1 < CH * POOL;
    int x00 = pw0 * psx - pad0x;
    int i00 = max(0, -x00), i01 = min(psx, lenx - x00);
    int x10 = pw1 * psx - pad0x;
    int i10 = max(0, -x10), i11 = min(psx, lenx - x10);
    bool padx0 = (pw0 * psx < pad0x) | ((pw0 + 1) * psx > pad0x + lenx);
    bool padx1 = (pw1 * psx < pad0x) | ((pw1 + 1) * psx > pad0x + lenx);
    const float* rp0 = cw + ch0 * CMW + x00 + dpx;
    const float* rp1 = cw + ch1 * CMW + x10 + dpx;
    int o0 = (n * C + cg * CH + ch0) * (POOL * POOL) + pw0;
    int o1 = (n * C + cg * CH + ch1) * (POOL * POOL) + pw1;

#define FM4(d, s) d.x = fmaxf(d.x, s.x); d.y = fmaxf(d.y, s.y); \
                  d.z = fmaxf(d.z, s.z); d.w = fmaxf(d.w, s.w)
#define LD4(q, off) __ldg((const float4*)((q) + (off)))

    for (int ph = 0; ph < POOL; ++ph) {
        int ys = max(0, ph * psy - pad0y);
        int ye = min(leny - 1, (ph + 1) * psy - 1 - pad0y);

        if (ys > ye) {                    // fully zero-padded row bin -> 0
            out[o0 + ph * POOL] = 0.0f;
            if (r1) out[o1 + ph * POOL] = 0.0f;
            continue;                     // warp-uniform
        }

        float4 a0 = make_float4(-INFINITY, -INFINITY, -INFINITY, -INFINITY);
        float4 a1 = a0, a2 = a0, a3 = a0;

        const float* p = bp + ys * W;
        int ry = ys;
        for (; ry + 1 <= ye; ry += 2) {   // 8 LDG.128 in flight
            if (act) {
                float4 u0 = LD4(p, 0);
                float4 u1 = LD4(p, 2 * H * W);
                float4 u2 = LD4(p, 4 * H * W);
                float4 u3 = LD4(p, 6 * H * W);
                float4 v0 = LD4(p, W);
                float4 v1 = LD4(p, W + 2 * H * W);
                float4 v2 = LD4(p, W + 4 * H * W);
                float4 v3 = LD4(p, W + 6 * H * W);
                FM4(u0, v0); FM4(u1, v1); FM4(u2, v2); FM4(u3, v3);
                FM4(a0, u0); FM4(a1, u1); FM4(a2, u2); FM4(a3, u3);
            }
            p += 2 * W;
        }
        if (ry <= ye && act) {
            float4 v0 = LD4(p, 0);
            float4 v1 = LD4(p, 2 * H * W);
            float4 v2 = LD4(p, 4 * H * W);
            float4 v3 = LD4(p, 6 * H * W);
            FM4(a0, v0); FM4(a1, v1); FM4(a2, v2); FM4(a3, v3);
        }

        // flush: step s holds plane 2s+h
        *(float4*)(cw + (0 + h) * CMW + 4 * li) = a0;
        *(float4*)(cw + (2 + h) * CMW + 4 * li) = a1;
        *(float4*)(cw + (4 + h) * CMW + 4 * li) = a2;
        *(float4*)(cw + (6 + h) * CMW + 4 * li) = a3;
        __syncwarp();

        bool pady = (ph * psy < pad0y) | ((ph + 1) * psy > pad0y + leny);
        {
            float mm = -INFINITY;
            for (int i = i00; i < i01; ++i) mm = fmaxf(mm, rp0[i]);
            if (padx0 | pady) mm = fmaxf(mm, 0.0f);
            if (!isfinite(mm)) mm = 0.0f; // fully-padded bin -> 0
            out[o0 + ph * POOL] = mm;
        }
        if (r1) {
            float mm = -INFINITY;
            for (int i = i10; i < i11; ++i) mm = fmaxf(mm, rp1[i]);
            if (padx1 | pady) mm = fmaxf(mm, 0.0f);
            if (!isfinite(mm)) mm = 0.0f;
            out[o1 + ph * POOL] = mm;
        }
        __syncwarp();
    }
#undef FM4
#undef LD4
}

extern "C" void kernel_launch(void* const* d_in, const int* in_sizes, int n_in,
                              void* d_out, int out_size) {
    const float* feat = (const float*)d_in[0];
    const float* rois = (const float*)d_in[1];
    float* out = (float*)d_out;

    const int C = 256;
    int N = in_sizes[1] / 5;

    int total = N * C * POOL * POOL;
    int write_bid = (out_size >= total + N) ? 1 : 0;

    dim3 grid(NGR / WPB, N);              // 4 x N blocks = 512
    roipool_kernel<<<grid, 32 * WPB>>>(feat, rois, out, N, C, write_bid);
}

// round 13
// speedup vs baseline: 1.2193x; 1.2193x over previous
#include <cuda_runtime.h>
#include <math.h>

#define POOL 7
#define ROI_SCALE 0.0625f
#define WPB 8        // warps per block
#define CH  8        // channels per warp
#define NGR 32       // channel groups = C/CH
#define CMW 68       // smem row pitch in floats (16B-aligned)
#define TPR (NGR * POOL)  // warp-tasks per ROI = 224

// grid = (TPR/WPB, N) = (28, N). Block owns one ROI (geometry decoded once by
// thread 0 into smem). Warp task = (8-channel group, row-bin). Lanes split:
// h = lane>>4 picks plane parity, li = lane&15 covers 64 cols as float4 ->
// 4 LDG.128 per row for all 8 planes (load step s = plane 2s+h), 2-row
// unrolled (8 LDG.128 in flight). Per bin: flush 4xSTS.128 to 2KB/warp smem,
// each lane reduces 2 of the 56 (ch,pw) outputs via x-direction segmented max.
__global__ __launch_bounds__(32 * WPB, 6)
void roipool_kernel(const float* __restrict__ feat,
                    const float* __restrict__ rois,
                    float* __restrict__ out,
                    int N, int C, int write_bid) {
    __shared__ float cm[WPB][CH * CMW];
    __shared__ int g[10];   // b,px,py,qx, lenx,leny, psx,psy, pad0x,pad0y
    const int H = 64, W = 64;

    int n = blockIdx.y;

    // Fused second output of the reference tuple: batch ids as floats.
    if (write_bid && blockIdx.x == 0 && blockIdx.y == 0 && threadIdx.x < N) {
        out[N * C * POOL * POOL + threadIdx.x] =
            (float)((int)rois[threadIdx.x * 5]);
    }

    if (threadIdx.x == 0) {
        const float* r = rois + n * 5;
        // jnp.round = round-half-to-even = __float2int_rn
        int px = __float2int_rn(r[1] * ROI_SCALE);
        int py = __float2int_rn(r[2] * ROI_SCALE);
        int qx = __float2int_rn(r[3] * ROI_SCALE);
        int qy = __float2int_rn(r[4] * ROI_SCALE);
        int lenx = max(qx - px + 1, 1);
        int leny = max(qy - py + 1, 1);
        int psx  = (lenx + POOL - 1) / POOL;
        int psy  = (leny + POOL - 1) / POOL;
        g[0] = (int)r[0];
        g[1] = px; g[2] = py; g[3] = qx;
        g[4] = lenx; g[5] = leny;
        g[6] = psx; g[7] = psy;
        g[8] = (psx * POOL - lenx) / 2;
        g[9] = (psy * POOL - leny) / 2;
    }
    __syncthreads();

    int warp = threadIdx.x >> 5;
    int lane = threadIdx.x & 31;
    int task = blockIdx.x * WPB + warp;   // 0..TPR-1
    int cg   = task & (NGR - 1);          // channel group (8 channels)
    int ph   = task >> 5;                 // row bin 0..6

    // --- minimal prologue for the mainloop ---
    int psy = g[7], pad0y = g[9], leny = g[5];
    int ys = max(0, ph * psy - pad0y);
    int ye = min(leny - 1, (ph + 1) * psy - 1 - pad0y);
    bool empty = ys > ye;                 // fully zero-padded row bin

    if (!empty) {
        int h  = lane >> 4;               // plane parity
        int li = lane & 15;               // float4 column index
        int px4 = g[1] & ~3;              // 16B-aligned load base
        bool act = (px4 + 4 * li) <= g[3];

        const float* p = feat
            + (unsigned)((g[0] * C + cg * CH + h) * (H * W))
            + (unsigned)((g[2] + ys) * W + px4 + 4 * li);

        float4 a0 = make_float4(-INFINITY, -INFINITY, -INFINITY, -INFINITY);
        float4 a1 = a0, a2 = a0, a3 = a0;

#define FM4(d, s) d.x = fmaxf(d.x, s.x); d.y = fmaxf(d.y, s.y); \
                  d.z = fmaxf(d.z, s.z); d.w = fmaxf(d.w, s.w)
#define LD4(q, off) __ldg((const float4*)((q) + (off)))
        int ry = ys;
        for (; ry + 1 <= ye; ry += 2) {   // 8 LDG.128 in flight
            if (act) {
                float4 u0 = LD4(p, 0);
                float4 u1 = LD4(p, 2 * H * W);
                float4 u2 = LD4(p, 4 * H * W);
                float4 u3 = LD4(p, 6 * H * W);
                float4 v0 = LD4(p, W);
                float4 v1 = LD4(p, W + 2 * H * W);
                float4 v2 = LD4(p, W + 4 * H * W);
                float4 v3 = LD4(p, W + 6 * H * W);
                FM4(u0, v0); FM4(u1, v1); FM4(u2, v2); FM4(u3, v3);
                FM4(a0, u0); FM4(a1, u1); FM4(a2, u2); FM4(a3, u3);
            }
            p += 2 * W;
        }
        if (ry <= ye && act) {
            float4 v0 = LD4(p, 0);
            float4 v1 = LD4(p, 2 * H * W);
            float4 v2 = LD4(p, 4 * H * W);
            float4 v3 = LD4(p, 6 * H * W);
            FM4(a0, v0); FM4(a1, v1); FM4(a2, v2); FM4(a3, v3);
        }
#undef FM4
#undef LD4

        // flush: load step s holds plane 2s+h
        float* cw = cm[warp];
        *(float4*)(cw + (0 + h) * CMW + 4 * li) = a0;
        *(float4*)(cw + (2 + h) * CMW + 4 * li) = a1;
        *(float4*)(cw + (4 + h) * CMW + 4 * li) = a2;
        *(float4*)(cw + (6 + h) * CMW + 4 * li) = a3;
        __syncwarp();
    }

    // --- epilogue: reduce roles computed here (not live across mainloop) ---
    int lenx = g[4], psx = g[6], pad0x = g[8];
    int dpx = g[1] & 3;                   // px - px4
    bool pady = (ph * psy < pad0y) | ((ph + 1) * psy > pad0y + leny);

    // Each lane owns 2 of the CH*POOL = 56 (ch,pw) outputs: lane and lane+32.
    int ch0 = lane / POOL, pw0 = lane - ch0 * POOL;   // const-div -> mul
    int bi1 = lane + 32;
    int ch1 = bi1 / POOL, pw1 = bi1 - ch1 * POOL;
    bool r1 = bi1 < CH * POOL;
    int ob = (n * C + cg * CH) * (POOL * POOL) + ph * POOL;
    int o0 = ob + ch0 * (POOL * POOL) + pw0;
    int o1 = ob + ch1 * (POOL * POOL) + pw1;

    if (empty) {
        out[o0] = 0.0f;
        if (r1) out[o1] = 0.0f;
        return;
    }

    const float* cw = cm[warp];
    {
        int x0 = pw0 * psx - pad0x;
        int i0 = max(0, -x0);
        int i1 = min(psx, lenx - x0);
        const float* rp = cw + ch0 * CMW + x0 + dpx;
        float mm = -INFINITY;
        for (int i = i0; i < i1; ++i) mm = fmaxf(mm, rp[i]);
        bool padx = (pw0 * psx < pad0x) | ((pw0 + 1) * psx > pad0x + lenx);
        if (padx | pady) mm = fmaxf(mm, 0.0f);
        if (!isfinite(mm)) mm = 0.0f;     // fully-padded bin -> 0
        out[o0] = mm;
    }
    if (r1) {
        int x0 = pw1 * psx - pad0x;
        int i0 = max(0, -x0);
        int i1 = min(psx, lenx - x0);
        const float* rp = cw + ch1 * CMW + x0 + dpx;
        float mm = -INFINITY;
        for (int i = i0; i < i1; ++i) mm = fmaxf(mm, rp[i]);
        bool padx = (pw1 * psx < pad0x) | ((pw1 + 1) * psx > pad0x + lenx);
        if (padx | pady) mm = fmaxf(mm, 0.0f);
        if (!isfinite(mm)) mm = 0.0f;
        out[o1] = mm;
    }
}

extern "C" void kernel_launch(void* const* d_in, const int* in_sizes, int n_in,
                              void* d_out, int out_size) {
    const float* feat = (const float*)d_in[0];
    const float* rois = (const float*)d_in[1];
    float* out = (float*)d_out;

    const int C = 256;
    int N = in_sizes[1] / 5;

    int total = N * C * POOL * POOL;
    int write_bid = (out_size >= total + N) ? 1 : 0;

    dim3 grid(TPR / WPB, N);              // 28 x N blocks
    roipool_kernel<<<grid, 32 * WPB>>>(feat, rois, out, N, C, write_bid);
}